// round 1
// baseline (speedup 1.0000x reference)
#include <cuda_runtime.h>

// Problem constants
#define NB   4096
#define NNUC 16
#define NELC 64
#define NF   128

// Element counts
#define S_LEN  8388608u      // NB*NNUC*NF
#define V_LEN  25165824u     // NB*NNUC*3*NF
#define E_LEN  4194304u      // NB*NNUC*NELC

// Output offsets (floats) in concatenated tuple order:
// s_flat, v_flat, edge_index(row), edge_index(col), edge_attr, mask
#define OFF_ROW  33554432u   // S_LEN + V_LEN
#define OFF_COL  37748736u   // + E_LEN
#define OFF_ATTR 41943040u   // + E_LEN
#define OFF_MASK 54525952u   // + 3*E_LEN

// One thread handles 4 consecutive pairs (same b, same nuc i, j0..j0+3).
// Total quads = E_LEN/4 = 1,048,576 -> 4096 blocks x 256 threads.
__global__ void __launch_bounds__(256)
edge_kernel(const float* __restrict__ ce,   // coord_elec [NB, NELC, 3]
            const float* __restrict__ cn,   // coord_nuc  [NNUC, 3]
            float* __restrict__ out)
{
    unsigned q  = blockIdx.x * 256u + threadIdx.x;  // quad index
    unsigned j0 = (q & 15u) * 4u;                   // elec base index within 64
    unsigned i  = (q >> 4) & 15u;                   // nuc index
    unsigned b  = q >> 8;                           // batch index
    unsigned p  = q * 4u;                           // pair base index

    // Nuclear coords: 48 floats total, fully cached (const/L1 path)
    float nx = __ldg(&cn[i * 3u + 0u]);
    float ny = __ldg(&cn[i * 3u + 1u]);
    float nz = __ldg(&cn[i * 3u + 2u]);

    // 4 electron coords = 12 contiguous floats, 48B-aligned -> 3x float4
    const float4* e4 =
        reinterpret_cast<const float4*>(ce + (size_t)(b * 64u + j0) * 3u);
    float4 e0 = __ldg(&e4[0]);
    float4 e1 = __ldg(&e4[1]);
    float4 e2 = __ldg(&e4[2]);

    float ex[4] = {e0.x, e0.w, e1.z, e2.y};
    float ey[4] = {e0.y, e1.x, e1.w, e2.z};
    float ez[4] = {e0.z, e1.y, e2.x, e2.w};

    float dx[4], dy[4], dz[4], m[4];
#pragma unroll
    for (int k = 0; k < 4; ++k) {
        dx[k] = ex[k] - nx;
        dy[k] = ey[k] - ny;
        dz[k] = ez[k] - nz;
        float d2 = dx[k] * dx[k] + dy[k] * dy[k] + dz[k] * dz[k];
        m[k] = (sqrtf(d2) < 5.0f) ? 1.0f : 0.0f;
    }

    float rowf = (float)(b * 16u + i);     // <= 65535, exact in f32
    float colb = (float)(b * 64u + j0);    // <= 262140, exact in f32

    // row: 4 identical values
    *reinterpret_cast<float4*>(out + OFF_ROW + p) =
        make_float4(rowf, rowf, rowf, rowf);
    // col: consecutive
    *reinterpret_cast<float4*>(out + OFF_COL + p) =
        make_float4(colb, colb + 1.0f, colb + 2.0f, colb + 3.0f);
    // attr: 12 contiguous floats, 48B-aligned -> 3x float4
    float4* a = reinterpret_cast<float4*>(out + OFF_ATTR + (size_t)p * 3u);
    a[0] = make_float4(dx[0], dy[0], dz[0], dx[1]);
    a[1] = make_float4(dy[1], dz[1], dx[2], dy[2]);
    a[2] = make_float4(dz[2], dx[3], dy[3], dz[3]);
    // mask as 0/1 floats
    *reinterpret_cast<float4*>(out + OFF_MASK + p) =
        make_float4(m[0], m[1], m[2], m[3]);
}

extern "C" void kernel_launch(void* const* d_in, const int* in_sizes, int n_in,
                              void* d_out, int out_size)
{
    // Identify inputs by element count (all four are distinct)
    const float* s  = nullptr;   // s_nuc      8,388,608
    const float* v  = nullptr;   // v_nuc     25,165,824
    const float* ce = nullptr;   // coord_elec   786,432
    const float* cn = nullptr;   // coord_nuc         48
    for (int k = 0; k < n_in; ++k) {
        switch (in_sizes[k]) {
            case 8388608:  s  = (const float*)d_in[k]; break;
            case 25165824: v  = (const float*)d_in[k]; break;
            case 786432:   ce = (const float*)d_in[k]; break;
            case 48:       cn = (const float*)d_in[k]; break;
            default: break;
        }
    }

    float* out = (float*)d_out;

    // s_flat / v_flat are pure reshapes: device-to-device async copies
    cudaMemcpyAsync(out, s, (size_t)S_LEN * sizeof(float),
                    cudaMemcpyDeviceToDevice, 0);
    cudaMemcpyAsync(out + S_LEN, v, (size_t)V_LEN * sizeof(float),
                    cudaMemcpyDeviceToDevice, 0);

    // edge_index / edge_attr / mask
    edge_kernel<<<4096, 256>>>(ce, cn, out);
}

// round 2
// speedup vs baseline: 1.1787x; 1.1787x over previous
#include <cuda_runtime.h>

// Problem constants
#define NB   4096
#define NNUC 16
#define NELC 64
#define NF   128

// Element counts (floats)
#define S_LEN  8388608u      // NB*NNUC*NF
#define V_LEN  25165824u     // NB*NNUC*3*NF
#define E_LEN  4194304u      // NB*NNUC*NELC

// Output offsets (floats): s_flat, v_flat, row, col, edge_attr, mask
#define OFF_V    8388608u
#define OFF_ROW  33554432u   // S_LEN + V_LEN
#define OFF_COL  37748736u   // + E_LEN
#define OFF_ATTR 41943040u   // + E_LEN
#define OFF_MASK 54525952u   // + 3*E_LEN

// float4 copy partition
#define S_F4          2097152u   // S_LEN/4
#define V_F4          6291456u   // V_LEN/4
#define S_COPY_BLOCKS 2048u      // * 1024 f4/block = S_F4
#define V_COPY_BLOCKS 6144u      // * 1024 f4/block = V_F4
#define COPY_BLOCKS   8192u
#define EDGE_BLOCKS   4096u      // one per batch b
#define TOTAL_BLOCKS  12288u

__global__ void __launch_bounds__(256)
fused_kernel(const float* __restrict__ s,
             const float* __restrict__ v,
             const float* __restrict__ ce,   // [NB, NELC, 3]
             const float* __restrict__ cn,   // [NNUC, 3]
             float* __restrict__ out)
{
    const unsigned blk = blockIdx.x;
    const unsigned tid = threadIdx.x;

    if (blk < COPY_BLOCKS) {
        // ---- pure reshape copies, fully coalesced float4, 4 f4/thread ----
        const float4* src4;
        float4* dst4;
        unsigned base;  // in float4 units within the region
        if (blk < S_COPY_BLOCKS) {
            src4 = reinterpret_cast<const float4*>(s);
            dst4 = reinterpret_cast<float4*>(out);
            base = blk * 1024u;
        } else {
            src4 = reinterpret_cast<const float4*>(v);
            dst4 = reinterpret_cast<float4*>(out + OFF_V);
            base = (blk - S_COPY_BLOCKS) * 1024u;
        }
#pragma unroll
        for (unsigned k = 0; k < 4; ++k) {
            unsigned idx = base + k * 256u + tid;
            dst4[idx] = __ldg(&src4[idx]);
        }
        return;
    }

    // ---- edge block: one batch b, everything generated from smem ----
    const unsigned b = blk - COPY_BLOCKS;

    __shared__ float ce_s[NELC * 3];   // 192 floats
    __shared__ float cn_s[NNUC * 3];   // 48 floats

    // stage coord_elec[b] (48 float4) and coord_nuc (12 float4), coalesced
    if (tid < 48u) {
        reinterpret_cast<float4*>(ce_s)[tid] =
            __ldg(reinterpret_cast<const float4*>(ce) + (size_t)b * 48u + tid);
    } else if (tid >= 64u && tid < 76u) {
        reinterpret_cast<float4*>(cn_s)[tid - 64u] =
            __ldg(reinterpret_cast<const float4*>(cn) + (tid - 64u));
    }
    __syncthreads();

    // ---- edge_attr: 768 float4 per batch, 3 per thread, coalesced stores ----
    // attr[b] flat float f = (i*64 + j)*3 + c ; value = ce_s[j*3+c] - cn_s[i*3+c]
    // float4 n covers floats 4n..4n+3, all within nucleus i = n/48,
    // elec-chunk float offset f0 = 4n - 192*i, component c = (f0+k) % 3.
    float4* attr4 = reinterpret_cast<float4*>(out + OFF_ATTR) + (size_t)b * 768u;
#pragma unroll
    for (unsigned k = 0; k < 3; ++k) {
        unsigned n  = k * 256u + tid;           // 0..767
        unsigned i  = n / 48u;                  // nucleus
        unsigned f0 = 4u * n - 192u * i;        // 0..188, multiple of 4
        float4 e = *reinterpret_cast<const float4*>(ce_s + f0);  // conflict-free
        const float* cni = cn_s + i * 3u;
        unsigned c0 = f0 % 3u;                  // component of lane 0
        // components cycle c0, c0+1, c0+2, c0  (mod 3)
        float n0 = cni[c0];
        float n1 = cni[(c0 + 1u) % 3u];
        float n2 = cni[(c0 + 2u) % 3u];
        float4 r;
        r.x = e.x - n0;
        r.y = e.y - n1;
        r.z = e.z - n2;
        r.w = e.w - n0;
        attr4[n] = r;
    }

    // ---- row / col / mask: 1024 pairs per batch, 4 per thread ----
    unsigned p0 = tid * 4u;            // pair index within batch (0..1023)
    unsigned i  = p0 >> 6;             // nucleus (4 pairs never cross i: 4 | 64)
    unsigned j0 = p0 & 63u;            // elec base

    float nx = cn_s[i * 3u + 0u];
    float ny = cn_s[i * 3u + 1u];
    float nz = cn_s[i * 3u + 2u];

    float m[4];
#pragma unroll
    for (unsigned k = 0; k < 4; ++k) {
        unsigned j = j0 + k;
        float dx = ce_s[j * 3u + 0u] - nx;
        float dy = ce_s[j * 3u + 1u] - ny;
        float dz = ce_s[j * 3u + 2u] - nz;
        float d2 = dx * dx + dy * dy + dz * dz;
        m[k] = (sqrtf(d2) < 5.0f) ? 1.0f : 0.0f;
    }

    float rowf = (float)(b * 16u + i);    // <= 65535, exact in f32
    float colb = (float)(b * 64u + j0);   // <= 262140, exact in f32

    size_t pb = (size_t)b * 1024u + p0;
    *reinterpret_cast<float4*>(out + OFF_ROW + pb) =
        make_float4(rowf, rowf, rowf, rowf);
    *reinterpret_cast<float4*>(out + OFF_COL + pb) =
        make_float4(colb, colb + 1.0f, colb + 2.0f, colb + 3.0f);
    *reinterpret_cast<float4*>(out + OFF_MASK + pb) =
        make_float4(m[0], m[1], m[2], m[3]);
}

extern "C" void kernel_launch(void* const* d_in, const int* in_sizes, int n_in,
                              void* d_out, int out_size)
{
    // Identify inputs by element count (all four are distinct)
    const float* s  = nullptr;   // s_nuc      8,388,608
    const float* v  = nullptr;   // v_nuc     25,165,824
    const float* ce = nullptr;   // coord_elec   786,432
    const float* cn = nullptr;   // coord_nuc         48
    for (int k = 0; k < n_in; ++k) {
        switch (in_sizes[k]) {
            case 8388608:  s  = (const float*)d_in[k]; break;
            case 25165824: v  = (const float*)d_in[k]; break;
            case 786432:   ce = (const float*)d_in[k]; break;
            case 48:       cn = (const float*)d_in[k]; break;
            default: break;
        }
    }

    fused_kernel<<<TOTAL_BLOCKS, 256>>>(s, v, ce, cn, (float*)d_out);
}

// round 3
// speedup vs baseline: 1.2041x; 1.0216x over previous
#include <cuda_runtime.h>

// Problem constants
#define NB   4096
#define NNUC 16
#define NELC 64
#define NF   128

// Output offsets (floats): s_flat, v_flat, row, col, edge_attr, mask
#define OFF_V    8388608u
#define OFF_ROW  33554432u
#define OFF_COL  37748736u
#define OFF_ATTR 41943040u
#define OFF_MASK 54525952u

// Copy partition: 8,388,608 float4 total (S: 2,097,152 then V: 6,291,456).
// 4096 blocks x 2048 f4/block. Blocks 0..1023 cover S exactly, 1024..4095 cover V.
#define COPY_F4_PER_BLK 2048u
#define S_BLOCKS        1024u

__global__ void __launch_bounds__(256)
fused_kernel(const float* __restrict__ s,
             const float* __restrict__ v,
             const float* __restrict__ ce,   // [NB, NELC, 3]
             const float* __restrict__ cn,   // [NNUC, 3]
             float* __restrict__ out)
{
    const unsigned b   = blockIdx.x;   // 0..4095 : batch AND copy-chunk id
    const unsigned tid = threadIdx.x;

    // ---------- issue copy loads early (8 independent LDG.128, streaming) ----
    const float4* src4;
    float4* dst4;
    unsigned base;
    if (b < S_BLOCKS) {
        src4 = reinterpret_cast<const float4*>(s);
        dst4 = reinterpret_cast<float4*>(out);
        base = b * COPY_F4_PER_BLK;
    } else {
        src4 = reinterpret_cast<const float4*>(v);
        dst4 = reinterpret_cast<float4*>(out + OFF_V);
        base = (b - S_BLOCKS) * COPY_F4_PER_BLK;
    }
    float4 c[8];
#pragma unroll
    for (unsigned k = 0; k < 8; ++k)
        c[k] = __ldcs(&src4[base + k * 256u + tid]);

    // ---------- stage coords into smem --------------------------------------
    __shared__ float ce_s[NELC * 3];   // 192 floats
    __shared__ float cn_s[NNUC * 3];   // 48 floats
    if (tid < 48u) {
        reinterpret_cast<float4*>(ce_s)[tid] =
            __ldg(reinterpret_cast<const float4*>(ce) + (size_t)b * 48u + tid);
    } else if (tid >= 64u && tid < 76u) {
        reinterpret_cast<float4*>(cn_s)[tid - 64u] =
            __ldg(reinterpret_cast<const float4*>(cn) + (tid - 64u));
    }
    __syncthreads();

    // ---------- edge_attr: 768 float4 per batch, 3 per thread ---------------
    // attr flat float f = (i*64 + j)*3 + c ; value = ce_s[j*3+c] - cn_s[i*3+c]
    float4* attr4 = reinterpret_cast<float4*>(out + OFF_ATTR) + (size_t)b * 768u;
#pragma unroll
    for (unsigned k = 0; k < 3; ++k) {
        unsigned n  = k * 256u + tid;           // 0..767
        unsigned i  = n / 48u;                  // nucleus
        unsigned f0 = 4u * n - 192u * i;        // elec-chunk float offset, %4==0
        float4 e = *reinterpret_cast<const float4*>(ce_s + f0);
        const float* cni = cn_s + i * 3u;
        unsigned c0 = f0 % 3u;
        float n0 = cni[c0];
        float n1 = cni[(c0 + 1u) % 3u];
        float n2 = cni[(c0 + 2u) % 3u];
        __stcs(&attr4[n], make_float4(e.x - n0, e.y - n1, e.z - n2, e.w - n0));
    }

    // ---------- row / col / mask: 1024 pairs per batch, 4 per thread --------
    unsigned p0 = tid * 4u;            // pair index within batch
    unsigned i  = p0 >> 6;             // nucleus (quads never cross i)
    unsigned j0 = p0 & 63u;

    float nx = cn_s[i * 3u + 0u];
    float ny = cn_s[i * 3u + 1u];
    float nz = cn_s[i * 3u + 2u];

    float m[4];
#pragma unroll
    for (unsigned k = 0; k < 4; ++k) {
        unsigned j = j0 + k;
        float dx = ce_s[j * 3u + 0u] - nx;
        float dy = ce_s[j * 3u + 1u] - ny;
        float dz = ce_s[j * 3u + 2u] - nz;
        float d2 = dx * dx + dy * dy + dz * dz;
        m[k] = (sqrtf(d2) < 5.0f) ? 1.0f : 0.0f;
    }

    float rowf = (float)(b * 16u + i);    // exact in f32
    float colb = (float)(b * 64u + j0);   // exact in f32

    size_t pb = (size_t)b * 1024u + p0;
    __stcs(reinterpret_cast<float4*>(out + OFF_ROW + pb),
           make_float4(rowf, rowf, rowf, rowf));
    __stcs(reinterpret_cast<float4*>(out + OFF_COL + pb),
           make_float4(colb, colb + 1.0f, colb + 2.0f, colb + 3.0f));
    __stcs(reinterpret_cast<float4*>(out + OFF_MASK + pb),
           make_float4(m[0], m[1], m[2], m[3]));

    // ---------- drain copy stores (streaming) -------------------------------
#pragma unroll
    for (unsigned k = 0; k < 8; ++k)
        __stcs(&dst4[base + k * 256u + tid], c[k]);
}

extern "C" void kernel_launch(void* const* d_in, const int* in_sizes, int n_in,
                              void* d_out, int out_size)
{
    const float* s  = nullptr;   // s_nuc      8,388,608
    const float* v  = nullptr;   // v_nuc     25,165,824
    const float* ce = nullptr;   // coord_elec   786,432
    const float* cn = nullptr;   // coord_nuc         48
    for (int k = 0; k < n_in; ++k) {
        switch (in_sizes[k]) {
            case 8388608:  s  = (const float*)d_in[k]; break;
            case 25165824: v  = (const float*)d_in[k]; break;
            case 786432:   ce = (const float*)d_in[k]; break;
            case 48:       cn = (const float*)d_in[k]; break;
            default: break;
        }
    }

    fused_kernel<<<NB, 256>>>(s, v, ce, cn, (float*)d_out);
}